// round 2
// baseline (speedup 1.0000x reference)
#include <cuda_runtime.h>
#include <cuda_bf16.h>
#include <math.h>

// Problem constants
#define B_   4
#define T_   2048
#define S_   2048
#define DQ_  512
#define DKV_ 1024
#define H_   8
#define HD_  64

// Scratch buffers (allocation-free: __device__ globals)
__device__ float g_Q[B_ * T_ * DQ_];     // [B,T,512]  (head-major inside: h*64+d)
__device__ float g_K[B_ * S_ * DQ_];
__device__ float g_V[B_ * S_ * DQ_];
__device__ float g_ctx[B_ * T_ * DQ_];

// ---------------------------------------------------------------------------
// Tiled fp32 GEMM with bias:  C[M,N] = A[M,K] @ W[K,N] + bias[N]
// BM=128, BN=64, BK=32, 256 threads, 8x4 per-thread microtile.
// ---------------------------------------------------------------------------
__global__ __launch_bounds__(256) void gemm_bias_kernel(
    const float* __restrict__ A, const float* __restrict__ W,
    const float* __restrict__ bias, float* __restrict__ C,
    int M, int N, int K)
{
    __shared__ float As[32][129];   // A tile, transposed [k][m]
    __shared__ float Ws[32][64];    // W tile [k][n]

    int tid = threadIdx.x;
    int bm = blockIdx.y * 128;
    int bn = blockIdx.x * 64;
    int tx = tid & 15;        // 16 -> 4 cols each
    int ty = tid >> 4;        // 16 -> 8 rows each

    float acc[8][4];
    #pragma unroll
    for (int i = 0; i < 8; i++)
        #pragma unroll
        for (int j = 0; j < 4; j++) acc[i][j] = 0.f;

    for (int k0 = 0; k0 < K; k0 += 32) {
        // A tile: consecutive threads read consecutive k -> coalesced 128B rows.
        #pragma unroll
        for (int i = tid; i < 128 * 32; i += 256) {
            int m = i >> 5, k = i & 31;
            As[k][m] = A[(size_t)(bm + m) * K + k0 + k];
        }
        // W tile: consecutive threads read consecutive n -> coalesced.
        #pragma unroll
        for (int i = tid; i < 32 * 64; i += 256) {
            int k = i >> 6, n = i & 63;
            Ws[k][n] = W[(size_t)(k0 + k) * N + bn + n];
        }
        __syncthreads();

        #pragma unroll
        for (int k = 0; k < 32; k++) {
            float a[8], w[4];
            #pragma unroll
            for (int i = 0; i < 8; i++) a[i] = As[k][ty * 8 + i];
            #pragma unroll
            for (int j = 0; j < 4; j++) w[j] = Ws[k][tx * 4 + j];
            #pragma unroll
            for (int i = 0; i < 8; i++)
                #pragma unroll
                for (int j = 0; j < 4; j++) acc[i][j] += a[i] * w[j];
        }
        __syncthreads();
    }

    #pragma unroll
    for (int i = 0; i < 8; i++) {
        int m = bm + ty * 8 + i;
        #pragma unroll
        for (int j = 0; j < 4; j++) {
            int n = bn + tx * 4 + j;
            C[(size_t)m * N + n] = acc[i][j] + bias[n];
        }
    }
}

// ---------------------------------------------------------------------------
// Scores: attn[b,h,t,s] = (Q[b,t,h,:] . K[b,s,h,:]) / 8 + attn_mask[t,s]
//         with key_padding_mask==0 -> -inf.
// GEMM over d (K-dim = 64, BK=32): BM=128 (t), BN=64 (s), 8x4 microtile.
// ---------------------------------------------------------------------------
__global__ __launch_bounds__(256) void score_kernel(
    const float* __restrict__ Q, const float* __restrict__ Kp,
    const float* __restrict__ attn_mask, const int* __restrict__ kpm,
    float* __restrict__ attn)
{
    int bh = blockIdx.z;
    int b = bh >> 3, h = bh & 7;
    int t0 = blockIdx.y * 128, s0 = blockIdx.x * 64;

    __shared__ float Qs[32][129];   // [d][t]  (transposed Q tile)
    __shared__ float Ks[32][65];    // [d][s]  (transposed K tile, padded)

    int tid = threadIdx.x;
    int tx = tid & 15, ty = tid >> 4;

    float acc[8][4];
    #pragma unroll
    for (int i = 0; i < 8; i++)
        #pragma unroll
        for (int j = 0; j < 4; j++) acc[i][j] = 0.f;

    for (int k0 = 0; k0 < HD_; k0 += 32) {
        // Q tile: consecutive threads -> consecutive d (coalesced).
        #pragma unroll
        for (int i = tid; i < 128 * 32; i += 256) {
            int m = i >> 5, d = i & 31;
            Qs[d][m] = Q[(size_t)(b * T_ + t0 + m) * DQ_ + h * HD_ + k0 + d];
        }
        // K tile: consecutive threads -> consecutive d (coalesced); padded store.
        #pragma unroll
        for (int i = tid; i < 64 * 32; i += 256) {
            int n = i >> 5, d = i & 31;
            Ks[d][n] = Kp[(size_t)(b * S_ + s0 + n) * DQ_ + h * HD_ + k0 + d];
        }
        __syncthreads();

        #pragma unroll
        for (int d = 0; d < 32; d++) {
            float a[8], k[4];
            #pragma unroll
            for (int i = 0; i < 8; i++) a[i] = Qs[d][ty * 8 + i];
            #pragma unroll
            for (int j = 0; j < 4; j++) k[j] = Ks[d][tx * 4 + j];
            #pragma unroll
            for (int i = 0; i < 8; i++)
                #pragma unroll
                for (int j = 0; j < 4; j++) acc[i][j] += a[i] * k[j];
        }
        __syncthreads();
    }

    #pragma unroll
    for (int i = 0; i < 8; i++) {
        int t = t0 + ty * 8 + i;
        #pragma unroll
        for (int j = 0; j < 4; j++) {
            int s = s0 + tx * 4 + j;
            float v = acc[i][j] * 0.125f + attn_mask[(size_t)t * S_ + s];
            if (kpm[b * S_ + s] == 0) v = -INFINITY;
            attn[(((size_t)bh * T_) + t) * S_ + s] = v;
        }
    }
}

// ---------------------------------------------------------------------------
// In-place row softmax over S=2048. One block per row; row in registers.
// ---------------------------------------------------------------------------
__global__ __launch_bounds__(256) void softmax_kernel(float* __restrict__ attn)
{
    size_t row = blockIdx.x;
    float* p = attn + row * (size_t)S_;
    int tid = threadIdx.x;

    float v[8];
    #pragma unroll
    for (int i = 0; i < 8; i++) v[i] = p[tid + 256 * i];

    // max reduce
    float m = v[0];
    #pragma unroll
    for (int i = 1; i < 8; i++) m = fmaxf(m, v[i]);
    #pragma unroll
    for (int o = 16; o > 0; o >>= 1) m = fmaxf(m, __shfl_xor_sync(0xffffffffu, m, o));

    __shared__ float red[8];
    if ((tid & 31) == 0) red[tid >> 5] = m;
    __syncthreads();
    if (tid < 32) {
        float x = (tid < 8) ? red[tid] : -INFINITY;
        #pragma unroll
        for (int o = 4; o > 0; o >>= 1) x = fmaxf(x, __shfl_xor_sync(0xffffffffu, x, o));
        if (tid == 0) red[0] = x;
    }
    __syncthreads();
    m = red[0];
    __syncthreads();

    // exp + sum
    float s = 0.f;
    #pragma unroll
    for (int i = 0; i < 8; i++) { v[i] = __expf(v[i] - m); s += v[i]; }
    #pragma unroll
    for (int o = 16; o > 0; o >>= 1) s += __shfl_xor_sync(0xffffffffu, s, o);
    if ((tid & 31) == 0) red[tid >> 5] = s;
    __syncthreads();
    if (tid < 32) {
        float x = (tid < 8) ? red[tid] : 0.f;
        #pragma unroll
        for (int o = 4; o > 0; o >>= 1) x += __shfl_xor_sync(0xffffffffu, x, o);
        if (tid == 0) red[0] = x;
    }
    __syncthreads();
    float inv = 1.0f / red[0];

    #pragma unroll
    for (int i = 0; i < 8; i++) p[tid + 256 * i] = v[i] * inv;
}

// ---------------------------------------------------------------------------
// ctx[b,t,h,:] = attn[b,h,t,:] @ V[b,:,h,:]   per (b,h)
// BM=128 (t), BN=64 (d), BK=32 over s, 8x4 microtile.
// ---------------------------------------------------------------------------
__global__ __launch_bounds__(256) void av_kernel(
    const float* __restrict__ attn, const float* __restrict__ Vp,
    float* __restrict__ ctx)
{
    int bh = blockIdx.y;
    int b = bh >> 3, h = bh & 7;
    int t0 = blockIdx.x * 128;

    __shared__ float As[32][129];   // attn tile transposed [s][t]
    __shared__ float Vs[32][64];    // V tile [s][d]

    int tid = threadIdx.x;
    int tx = tid & 15, ty = tid >> 4;

    float acc[8][4];
    #pragma unroll
    for (int i = 0; i < 8; i++)
        #pragma unroll
        for (int j = 0; j < 4; j++) acc[i][j] = 0.f;

    const float* arow = attn + ((size_t)bh * T_ + t0) * S_;

    for (int k0 = 0; k0 < S_; k0 += 32) {
        // attn tile: consecutive threads -> consecutive s (coalesced).
        #pragma unroll
        for (int i = tid; i < 128 * 32; i += 256) {
            int m = i >> 5, k = i & 31;
            As[k][m] = arow[(size_t)m * S_ + k0 + k];
        }
        // V tile: consecutive threads -> consecutive d (coalesced).
        #pragma unroll
        for (int i = tid; i < 32 * 64; i += 256) {
            int k = i >> 6, d = i & 63;
            Vs[k][d] = Vp[(size_t)(b * S_ + k0 + k) * DQ_ + h * HD_ + d];
        }
        __syncthreads();

        #pragma unroll
        for (int k = 0; k < 32; k++) {
            float a[8], vv[4];
            #pragma unroll
            for (int i = 0; i < 8; i++) a[i] = As[k][ty * 8 + i];
            #pragma unroll
            for (int j = 0; j < 4; j++) vv[j] = Vs[k][tx * 4 + j];
            #pragma unroll
            for (int i = 0; i < 8; i++)
                #pragma unroll
                for (int j = 0; j < 4; j++) acc[i][j] += a[i] * vv[j];
        }
        __syncthreads();
    }

    #pragma unroll
    for (int i = 0; i < 8; i++) {
        int t = t0 + ty * 8 + i;
        #pragma unroll
        for (int j = 0; j < 4; j++) {
            int d = tx * 4 + j;
            ctx[(size_t)(b * T_ + t) * DQ_ + h * HD_ + d] = acc[i][j];
        }
    }
}

// ---------------------------------------------------------------------------
// Launch
// ---------------------------------------------------------------------------
extern "C" void kernel_launch(void* const* d_in, const int* in_sizes, int n_in,
                              void* d_out, int out_size)
{
    const float* query     = (const float*)d_in[0];
    const float* key       = (const float*)d_in[1];
    const float* value     = (const float*)d_in[2];
    const int*   kpm       = (const int*)  d_in[3];
    const float* attn_mask = (const float*)d_in[4];
    const float* Wq = (const float*)d_in[5];
    const float* bq = (const float*)d_in[6];
    const float* Wk = (const float*)d_in[7];
    const float* bk = (const float*)d_in[8];
    const float* Wv = (const float*)d_in[9];
    const float* bv = (const float*)d_in[10];
    const float* Wo = (const float*)d_in[11];
    const float* bo = (const float*)d_in[12];

    float* out  = (float*)d_out;                        // [B,T,DQ]
    float* attn = out + (size_t)B_ * T_ * DQ_;          // [B,H,T,S]

    float *Qp, *Kp, *Vp, *Cp;
    cudaGetSymbolAddress((void**)&Qp, g_Q);
    cudaGetSymbolAddress((void**)&Kp, g_K);
    cudaGetSymbolAddress((void**)&Vp, g_V);
    cudaGetSymbolAddress((void**)&Cp, g_ctx);

    const int M = B_ * T_;   // 8192

    // Projections
    gemm_bias_kernel<<<dim3(DQ_ / 64, M / 128), 256>>>(query, Wq, bq, Qp, M, DQ_, DQ_);
    gemm_bias_kernel<<<dim3(DQ_ / 64, M / 128), 256>>>(key,   Wk, bk, Kp, M, DQ_, DKV_);
    gemm_bias_kernel<<<dim3(DQ_ / 64, M / 128), 256>>>(value, Wv, bv, Vp, M, DQ_, DKV_);

    // Scores + mask -> attn region of d_out
    score_kernel<<<dim3(S_ / 64, T_ / 128, B_ * H_), 256>>>(Qp, Kp, attn_mask, kpm, attn);

    // Row softmax in place
    softmax_kernel<<<B_ * H_ * T_, 256>>>(attn);

    // attn @ V -> ctx
    av_kernel<<<dim3(T_ / 128, B_ * H_), 256>>>(attn, Vp, Cp);

    // Output projection
    gemm_bias_kernel<<<dim3(DQ_ / 64, M / 128), 256>>>(Cp, Wo, bo, out, M, DQ_, DQ_);
}

// round 3
// speedup vs baseline: 1.5220x; 1.5220x over previous
#include <cuda_runtime.h>
#include <cuda_bf16.h>
#include <math.h>
#include <stdint.h>

// Problem constants
#define B_   4
#define T_   2048
#define S_   2048
#define DQ_  512
#define DKV_ 1024
#define H_   8
#define HD_  64

// Scratch buffers (allocation-free: __device__ globals)
__device__ float g_Q[B_ * T_ * DQ_];     // [B,T,512]  (head-major inside: h*64+d)
__device__ float g_K[B_ * S_ * DQ_];
__device__ float g_V[B_ * S_ * DQ_];
__device__ float g_ctx[B_ * T_ * DQ_];

// ---------------------------------------------------------------------------
// tf32 helpers
// ---------------------------------------------------------------------------
__device__ __forceinline__ uint32_t f2tf32(float f) {
    uint32_t r;
    asm("cvt.rna.tf32.f32 %0, %1;" : "=r"(r) : "f"(f));
    return r;
}

__device__ __forceinline__ void mma_tf32(float d[4],
                                         uint32_t a0, uint32_t a1, uint32_t a2, uint32_t a3,
                                         uint32_t b0, uint32_t b1) {
    asm volatile(
        "mma.sync.aligned.m16n8k8.row.col.f32.tf32.tf32.f32 "
        "{%0,%1,%2,%3}, {%4,%5,%6,%7}, {%8,%9}, {%0,%1,%2,%3};\n"
        : "+f"(d[0]), "+f"(d[1]), "+f"(d[2]), "+f"(d[3])
        : "r"(a0), "r"(a1), "r"(a2), "r"(a3), "r"(b0), "r"(b1));
}

// Warp tiling shared by all GEMMs:
//   block tile 128(M) x 64(N), BK=32, 256 threads = 8 warps
//   warp grid 4(M) x 2(N): warp tile 32x32
//   per warp: 2 m-subtiles (16) x 4 n-subtiles (8), k in steps of 8.
// Fragment mapping (m16n8k8): g = lane>>2, tg = lane&3.
//   A: a0=[g][tg] a1=[g+8][tg] a2=[g][tg+4] a3=[g+8][tg+4]
//   B: b0=[tg][g] b1=[tg+4][g]
//   C: c0=[g][2tg] c1=[g][2tg+1] c2=[g+8][2tg] c3=[g+8][2tg+1]

// ---------------------------------------------------------------------------
// Projections / output:  C[M,N] = A[M,K] @ W[K,N] + bias[N]   (W is k-major)
// ---------------------------------------------------------------------------
__global__ __launch_bounds__(256) void gemm_bias_tc(
    const float* __restrict__ A, const float* __restrict__ W,
    const float* __restrict__ bias, float* __restrict__ C,
    int M, int N, int K)
{
    __shared__ uint32_t As[128][36];   // [m][k], pad 36 -> conflict-free frags
    __shared__ uint32_t Bs[32][68];    // [k][n], pad 68 -> conflict-free frags

    const int tid = threadIdx.x;
    const int wid = tid >> 5, lane = tid & 31;
    const int g = lane >> 2, tg = lane & 3;
    const int bm = blockIdx.y * 128, bn = blockIdx.x * 64;
    const int wm = (wid >> 1) * 32, wn = (wid & 1) * 32;

    float acc[2][4][4];
    #pragma unroll
    for (int mt = 0; mt < 2; mt++)
        #pragma unroll
        for (int nt = 0; nt < 4; nt++)
            #pragma unroll
            for (int r = 0; r < 4; r++) acc[mt][nt][r] = 0.f;

    for (int k0 = 0; k0 < K; k0 += 32) {
        #pragma unroll
        for (int i = tid; i < 128 * 32; i += 256) {
            int m = i >> 5, k = i & 31;
            As[m][k] = f2tf32(A[(size_t)(bm + m) * K + k0 + k]);
        }
        #pragma unroll
        for (int i = tid; i < 32 * 64; i += 256) {
            int k = i >> 6, n = i & 63;
            Bs[k][n] = f2tf32(W[(size_t)(k0 + k) * N + bn + n]);
        }
        __syncthreads();

        #pragma unroll
        for (int ks = 0; ks < 4; ks++) {
            const int kk = ks * 8;
            uint32_t a[2][4], b[4][2];
            #pragma unroll
            for (int mt = 0; mt < 2; mt++) {
                int mr = wm + mt * 16;
                a[mt][0] = As[mr + g][kk + tg];
                a[mt][1] = As[mr + g + 8][kk + tg];
                a[mt][2] = As[mr + g][kk + tg + 4];
                a[mt][3] = As[mr + g + 8][kk + tg + 4];
            }
            #pragma unroll
            for (int nt = 0; nt < 4; nt++) {
                int nc = wn + nt * 8 + g;
                b[nt][0] = Bs[kk + tg][nc];
                b[nt][1] = Bs[kk + tg + 4][nc];
            }
            #pragma unroll
            for (int mt = 0; mt < 2; mt++)
                #pragma unroll
                for (int nt = 0; nt < 4; nt++)
                    mma_tf32(acc[mt][nt], a[mt][0], a[mt][1], a[mt][2], a[mt][3],
                             b[nt][0], b[nt][1]);
        }
        __syncthreads();
    }

    #pragma unroll
    for (int mt = 0; mt < 2; mt++) {
        #pragma unroll
        for (int nt = 0; nt < 4; nt++) {
            int n0 = bn + wn + nt * 8 + tg * 2;
            float b0v = bias[n0], b1v = bias[n0 + 1];
            int r0 = bm + wm + mt * 16 + g;
            C[(size_t)r0 * N + n0]           = acc[mt][nt][0] + b0v;
            C[(size_t)r0 * N + n0 + 1]       = acc[mt][nt][1] + b1v;
            C[(size_t)(r0 + 8) * N + n0]     = acc[mt][nt][2] + b0v;
            C[(size_t)(r0 + 8) * N + n0 + 1] = acc[mt][nt][3] + b1v;
        }
    }
}

// ---------------------------------------------------------------------------
// Scores: attn[b,h,t,s] = (Q[b,t,h,:].K[b,s,h,:]) / 8 + attn_mask[t,s]
//         kpm==0 -> -inf.   M=128(t) x N=64(s), K=HD=64, B is n-major (K rows).
// ---------------------------------------------------------------------------
__global__ __launch_bounds__(256) void score_tc(
    const float* __restrict__ Q, const float* __restrict__ Kp,
    const float* __restrict__ attn_mask, const int* __restrict__ kpm,
    float* __restrict__ attn)
{
    __shared__ uint32_t As[128][36];   // Q tile [t][d]
    __shared__ uint32_t Ks[64][36];    // K tile [s][d] (n-major)

    const int tid = threadIdx.x;
    const int wid = tid >> 5, lane = tid & 31;
    const int g = lane >> 2, tg = lane & 3;
    const int bh = blockIdx.z;
    const int b = bh >> 3, h = bh & 7;
    const int t0 = blockIdx.y * 128, s0 = blockIdx.x * 64;
    const int wm = (wid >> 1) * 32, wn = (wid & 1) * 32;

    float acc[2][4][4];
    #pragma unroll
    for (int mt = 0; mt < 2; mt++)
        #pragma unroll
        for (int nt = 0; nt < 4; nt++)
            #pragma unroll
            for (int r = 0; r < 4; r++) acc[mt][nt][r] = 0.f;

    for (int k0 = 0; k0 < HD_; k0 += 32) {
        #pragma unroll
        for (int i = tid; i < 128 * 32; i += 256) {
            int m = i >> 5, k = i & 31;
            As[m][k] = f2tf32(Q[(size_t)(b * T_ + t0 + m) * DQ_ + h * HD_ + k0 + k]);
        }
        #pragma unroll
        for (int i = tid; i < 64 * 32; i += 256) {
            int n = i >> 5, k = i & 31;
            Ks[n][k] = f2tf32(Kp[(size_t)(b * S_ + s0 + n) * DQ_ + h * HD_ + k0 + k]);
        }
        __syncthreads();

        #pragma unroll
        for (int ks = 0; ks < 4; ks++) {
            const int kk = ks * 8;
            uint32_t a[2][4], bfr[4][2];
            #pragma unroll
            for (int mt = 0; mt < 2; mt++) {
                int mr = wm + mt * 16;
                a[mt][0] = As[mr + g][kk + tg];
                a[mt][1] = As[mr + g + 8][kk + tg];
                a[mt][2] = As[mr + g][kk + tg + 4];
                a[mt][3] = As[mr + g + 8][kk + tg + 4];
            }
            #pragma unroll
            for (int nt = 0; nt < 4; nt++) {
                int nc = wn + nt * 8 + g;
                bfr[nt][0] = Ks[nc][kk + tg];
                bfr[nt][1] = Ks[nc][kk + tg + 4];
            }
            #pragma unroll
            for (int mt = 0; mt < 2; mt++)
                #pragma unroll
                for (int nt = 0; nt < 4; nt++)
                    mma_tf32(acc[mt][nt], a[mt][0], a[mt][1], a[mt][2], a[mt][3],
                             bfr[nt][0], bfr[nt][1]);
        }
        __syncthreads();
    }

    // Epilogue: scale + mask + kpm
    #pragma unroll
    for (int mt = 0; mt < 2; mt++) {
        #pragma unroll
        for (int nt = 0; nt < 4; nt++) {
            int s = s0 + wn + nt * 8 + tg * 2;
            int kp0 = kpm[b * S_ + s], kp1 = kpm[b * S_ + s + 1];
            int t = t0 + wm + mt * 16 + g;
            #pragma unroll
            for (int half = 0; half < 2; half++) {
                int tr = t + half * 8;
                float v0 = acc[mt][nt][half * 2]     * 0.125f + attn_mask[(size_t)tr * S_ + s];
                float v1 = acc[mt][nt][half * 2 + 1] * 0.125f + attn_mask[(size_t)tr * S_ + s + 1];
                if (kp0 == 0) v0 = -INFINITY;
                if (kp1 == 0) v1 = -INFINITY;
                attn[((size_t)bh * T_ + tr) * S_ + s]     = v0;
                attn[((size_t)bh * T_ + tr) * S_ + s + 1] = v1;
            }
        }
    }
}

// ---------------------------------------------------------------------------
// In-place row softmax over S=2048. One block per row; row in registers.
// ---------------------------------------------------------------------------
__global__ __launch_bounds__(256) void softmax_kernel(float* __restrict__ attn)
{
    size_t row = blockIdx.x;
    float* p = attn + row * (size_t)S_;
    int tid = threadIdx.x;

    float v[8];
    #pragma unroll
    for (int i = 0; i < 8; i++) v[i] = p[tid + 256 * i];

    float m = v[0];
    #pragma unroll
    for (int i = 1; i < 8; i++) m = fmaxf(m, v[i]);
    #pragma unroll
    for (int o = 16; o > 0; o >>= 1) m = fmaxf(m, __shfl_xor_sync(0xffffffffu, m, o));

    __shared__ float red[8];
    if ((tid & 31) == 0) red[tid >> 5] = m;
    __syncthreads();
    if (tid < 32) {
        float x = (tid < 8) ? red[tid] : -INFINITY;
        #pragma unroll
        for (int o = 4; o > 0; o >>= 1) x = fmaxf(x, __shfl_xor_sync(0xffffffffu, x, o));
        if (tid == 0) red[0] = x;
    }
    __syncthreads();
    m = red[0];
    __syncthreads();

    float s = 0.f;
    #pragma unroll
    for (int i = 0; i < 8; i++) { v[i] = __expf(v[i] - m); s += v[i]; }
    #pragma unroll
    for (int o = 16; o > 0; o >>= 1) s += __shfl_xor_sync(0xffffffffu, s, o);
    if ((tid & 31) == 0) red[tid >> 5] = s;
    __syncthreads();
    if (tid < 32) {
        float x = (tid < 8) ? red[tid] : 0.f;
        #pragma unroll
        for (int o = 4; o > 0; o >>= 1) x += __shfl_xor_sync(0xffffffffu, x, o);
        if (tid == 0) red[0] = x;
    }
    __syncthreads();
    float inv = 1.0f / red[0];

    #pragma unroll
    for (int i = 0; i < 8; i++) p[tid + 256 * i] = v[i] * inv;
}

// ---------------------------------------------------------------------------
// ctx[b,t,h,:] = attn[b,h,t,:] @ V[b,:,h,:]    M=128(t) x N=64(d), K=S=2048
// ---------------------------------------------------------------------------
__global__ __launch_bounds__(256) void av_tc(
    const float* __restrict__ attn, const float* __restrict__ Vp,
    float* __restrict__ ctx)
{
    __shared__ uint32_t As[128][36];   // attn tile [t][s]
    __shared__ uint32_t Bs[32][68];    // V tile [s][d] (k-major)

    const int tid = threadIdx.x;
    const int wid = tid >> 5, lane = tid & 31;
    const int g = lane >> 2, tg = lane & 3;
    const int bh = blockIdx.y;
    const int b = bh >> 3, h = bh & 7;
    const int t0 = blockIdx.x * 128;
    const int wm = (wid >> 1) * 32, wn = (wid & 1) * 32;

    float acc[2][4][4];
    #pragma unroll
    for (int mt = 0; mt < 2; mt++)
        #pragma unroll
        for (int nt = 0; nt < 4; nt++)
            #pragma unroll
            for (int r = 0; r < 4; r++) acc[mt][nt][r] = 0.f;

    const float* arow = attn + ((size_t)bh * T_ + t0) * S_;

    for (int k0 = 0; k0 < S_; k0 += 32) {
        #pragma unroll
        for (int i = tid; i < 128 * 32; i += 256) {
            int m = i >> 5, k = i & 31;
            As[m][k] = f2tf32(arow[(size_t)m * S_ + k0 + k]);
        }
        #pragma unroll
        for (int i = tid; i < 32 * 64; i += 256) {
            int k = i >> 6, n = i & 63;
            Bs[k][n] = f2tf32(Vp[(size_t)(b * S_ + k0 + k) * DQ_ + h * HD_ + n]);
        }
        __syncthreads();

        #pragma unroll
        for (int ks = 0; ks < 4; ks++) {
            const int kk = ks * 8;
            uint32_t a[2][4], bfr[4][2];
            #pragma unroll
            for (int mt = 0; mt < 2; mt++) {
                int mr = wm + mt * 16;
                a[mt][0] = As[mr + g][kk + tg];
                a[mt][1] = As[mr + g + 8][kk + tg];
                a[mt][2] = As[mr + g][kk + tg + 4];
                a[mt][3] = As[mr + g + 8][kk + tg + 4];
            }
            #pragma unroll
            for (int nt = 0; nt < 4; nt++) {
                int nc = wn + nt * 8 + g;
                bfr[nt][0] = Bs[kk + tg][nc];
                bfr[nt][1] = Bs[kk + tg + 4][nc];
            }
            #pragma unroll
            for (int mt = 0; mt < 2; mt++)
                #pragma unroll
                for (int nt = 0; nt < 4; nt++)
                    mma_tf32(acc[mt][nt], a[mt][0], a[mt][1], a[mt][2], a[mt][3],
                             bfr[nt][0], bfr[nt][1]);
        }
        __syncthreads();
    }

    #pragma unroll
    for (int mt = 0; mt < 2; mt++) {
        #pragma unroll
        for (int nt = 0; nt < 4; nt++) {
            int d0 = wn + nt * 8 + tg * 2;
            int t = t0 + wm + mt * 16 + g;
            ctx[(size_t)(b * T_ + t) * DQ_ + h * HD_ + d0]           = acc[mt][nt][0];
            ctx[(size_t)(b * T_ + t) * DQ_ + h * HD_ + d0 + 1]       = acc[mt][nt][1];
            ctx[(size_t)(b * T_ + t + 8) * DQ_ + h * HD_ + d0]       = acc[mt][nt][2];
            ctx[(size_t)(b * T_ + t + 8) * DQ_ + h * HD_ + d0 + 1]   = acc[mt][nt][3];
        }
    }
}

// ---------------------------------------------------------------------------
// Launch
// ---------------------------------------------------------------------------
extern "C" void kernel_launch(void* const* d_in, const int* in_sizes, int n_in,
                              void* d_out, int out_size)
{
    const float* query     = (const float*)d_in[0];
    const float* key       = (const float*)d_in[1];
    const float* value     = (const float*)d_in[2];
    const int*   kpm       = (const int*)  d_in[3];
    const float* attn_mask = (const float*)d_in[4];
    const float* Wq = (const float*)d_in[5];
    const float* bq = (const float*)d_in[6];
    const float* Wk = (const float*)d_in[7];
    const float* bk = (const float*)d_in[8];
    const float* Wv = (const float*)d_in[9];
    const float* bv = (const float*)d_in[10];
    const float* Wo = (const float*)d_in[11];
    const float* bo = (const float*)d_in[12];

    float* out  = (float*)d_out;                        // [B,T,DQ]
    float* attn = out + (size_t)B_ * T_ * DQ_;          // [B,H,T,S]

    float *Qp, *Kp, *Vp, *Cp;
    cudaGetSymbolAddress((void**)&Qp, g_Q);
    cudaGetSymbolAddress((void**)&Kp, g_K);
    cudaGetSymbolAddress((void**)&Vp, g_V);
    cudaGetSymbolAddress((void**)&Cp, g_ctx);

    const int M = B_ * T_;   // 8192

    // Projections (tf32 tensor cores)
    gemm_bias_tc<<<dim3(DQ_ / 64, M / 128), 256>>>(query, Wq, bq, Qp, M, DQ_, DQ_);
    gemm_bias_tc<<<dim3(DQ_ / 64, M / 128), 256>>>(key,   Wk, bk, Kp, M, DQ_, DKV_);
    gemm_bias_tc<<<dim3(DQ_ / 64, M / 128), 256>>>(value, Wv, bv, Vp, M, DQ_, DKV_);

    // Scores + mask -> attn region of d_out
    score_tc<<<dim3(S_ / 64, T_ / 128, B_ * H_), 256>>>(Qp, Kp, attn_mask, kpm, attn);

    // Row softmax in place
    softmax_kernel<<<B_ * H_ * T_, 256>>>(attn);

    // attn @ V -> ctx
    av_tc<<<dim3(T_ / 128, B_ * H_), 256>>>(attn, Vp, Cp);

    // Output projection
    gemm_bias_tc<<<dim3(DQ_ / 64, M / 128), 256>>>(Cp, Wo, bo, out, M, DQ_, DQ_);
}

// round 4
// speedup vs baseline: 2.3685x; 1.5562x over previous
#include <cuda_runtime.h>
#include <cuda_bf16.h>
#include <math.h>
#include <stdint.h>

// Problem constants
#define B_   4
#define T_   2048
#define S_   2048
#define DQ_  512
#define DKV_ 1024
#define H_   8
#define HD_  64

// Scratch buffers (allocation-free: __device__ globals)
__device__ float g_Q[B_ * T_ * DQ_];
__device__ float g_K[B_ * S_ * DQ_];
__device__ float g_V[B_ * S_ * DQ_];
__device__ float g_ctx[B_ * T_ * DQ_];

// ---------------------------------------------------------------------------
// Helpers
// ---------------------------------------------------------------------------
__device__ __forceinline__ uint32_t f2tf32(float f) {
    uint32_t r;
    asm("cvt.rna.tf32.f32 %0, %1;" : "=r"(r) : "f"(f));
    return r;
}
__device__ __forceinline__ uint32_t ldtf(const float* p) { return f2tf32(*p); }

__device__ __forceinline__ void mma_tf32(float d[4],
                                         uint32_t a0, uint32_t a1, uint32_t a2, uint32_t a3,
                                         uint32_t b0, uint32_t b1) {
    asm volatile(
        "mma.sync.aligned.m16n8k8.row.col.f32.tf32.tf32.f32 "
        "{%0,%1,%2,%3}, {%4,%5,%6,%7}, {%8,%9}, {%0,%1,%2,%3};\n"
        : "+f"(d[0]), "+f"(d[1]), "+f"(d[2]), "+f"(d[3])
        : "r"(a0), "r"(a1), "r"(a2), "r"(a3), "r"(b0), "r"(b1));
}

__device__ __forceinline__ void cp_async16(uint32_t s, const void* g) {
    asm volatile("cp.async.cg.shared.global [%0], [%1], 16;\n" :: "r"(s), "l"(g));
}
__device__ __forceinline__ void cp_commit() { asm volatile("cp.async.commit_group;\n" ::: "memory"); }
__device__ __forceinline__ void cp_wait0()  { asm volatile("cp.async.wait_group 0;\n" ::: "memory"); }

// Fragment mapping (m16n8k8 tf32): g = lane>>2, tg = lane&3.
//   A row-major [m][k]: a0=[g][tg] a1=[g+8][tg] a2=[g][tg+4] a3=[g+8][tg+4]
//   B col-major: b0=[k=tg][n=g] b1=[k=tg+4][n=g]
//   C: c0=[g][2tg] c1=[g][2tg+1] c2=[g+8][2tg] c3=[g+8][2tg+1]
// Warp tile 64(M)x32(N): 4 m-subtiles x 4 n-subtiles, 16 mmas / 8-kstep.

// ---------------------------------------------------------------------------
// Projections / output:  C[M,N] = A[M,K] @ W[K,N] + bias[N]
// Block 128x64, 4 warps (2x2), BK=32, cp.async double-buffered.
// Dynamic smem: A [2][128][36] fp32, B [2][32][68] fp32 = 54272 B.
// ---------------------------------------------------------------------------
__global__ __launch_bounds__(128, 4) void gemm_bias_tc(
    const float* __restrict__ A, const float* __restrict__ W,
    const float* __restrict__ bias, float* __restrict__ C,
    int M, int N, int K)
{
    extern __shared__ float dsm[];
    float* As = dsm;                    // [2][128][36]
    float* Bs = dsm + 2 * 128 * 36;     // [2][32][68]
    const uint32_t abase = (uint32_t)__cvta_generic_to_shared(As);
    const uint32_t bbase = (uint32_t)__cvta_generic_to_shared(Bs);

    const int tid = threadIdx.x;
    const int wid = tid >> 5, lane = tid & 31;
    const int g = lane >> 2, tg = lane & 3;
    const int bm = blockIdx.y * 128, bn = blockIdx.x * 64;
    const int wm = (wid >> 1) * 64, wn = (wid & 1) * 32;

    float acc[4][4][4];
    #pragma unroll
    for (int mt = 0; mt < 4; mt++)
        #pragma unroll
        for (int nt = 0; nt < 4; nt++)
            #pragma unroll
            for (int r = 0; r < 4; r++) acc[mt][nt][r] = 0.f;

    // stage loader
    auto load_stage = [&](int buf, int k0) {
        uint32_t ab = abase + (uint32_t)buf * 128 * 36 * 4;
        #pragma unroll
        for (int i = tid; i < 128 * 8; i += 128) {       // A: 128 rows x 128B
            int r = i >> 3, seg = i & 7;
            cp_async16(ab + (r * 36 + seg * 4) * 4,
                       A + (size_t)(bm + r) * K + k0 + seg * 4);
        }
        uint32_t bb = bbase + (uint32_t)buf * 32 * 68 * 4;
        #pragma unroll
        for (int i = tid; i < 32 * 16; i += 128) {       // W: 32 rows x 256B
            int r = i >> 4, seg = i & 15;
            cp_async16(bb + (r * 68 + seg * 4) * 4,
                       W + (size_t)(k0 + r) * N + bn + seg * 4);
        }
        cp_commit();
    };

    load_stage(0, 0);
    int buf = 0;
    for (int k0 = 0; k0 < K; k0 += 32, buf ^= 1) {
        cp_wait0();
        __syncthreads();
        if (k0 + 32 < K) load_stage(buf ^ 1, k0 + 32);

        const float* Ab = As + buf * 128 * 36;
        const float* Bb = Bs + buf * 32 * 68;
        #pragma unroll
        for (int ks = 0; ks < 4; ks++) {
            const int kk = ks * 8;
            uint32_t a[4][4], bf[4][2];
            #pragma unroll
            for (int mt = 0; mt < 4; mt++) {
                int mr = wm + mt * 16;
                a[mt][0] = ldtf(Ab + (mr + g) * 36 + kk + tg);
                a[mt][1] = ldtf(Ab + (mr + g + 8) * 36 + kk + tg);
                a[mt][2] = ldtf(Ab + (mr + g) * 36 + kk + tg + 4);
                a[mt][3] = ldtf(Ab + (mr + g + 8) * 36 + kk + tg + 4);
            }
            #pragma unroll
            for (int nt = 0; nt < 4; nt++) {
                int nc = wn + nt * 8 + g;
                bf[nt][0] = ldtf(Bb + (kk + tg) * 68 + nc);
                bf[nt][1] = ldtf(Bb + (kk + tg + 4) * 68 + nc);
            }
            #pragma unroll
            for (int mt = 0; mt < 4; mt++)
                #pragma unroll
                for (int nt = 0; nt < 4; nt++)
                    mma_tf32(acc[mt][nt], a[mt][0], a[mt][1], a[mt][2], a[mt][3],
                             bf[nt][0], bf[nt][1]);
        }
    }

    #pragma unroll
    for (int mt = 0; mt < 4; mt++) {
        #pragma unroll
        for (int nt = 0; nt < 4; nt++) {
            int n0 = bn + wn + nt * 8 + tg * 2;
            float b0v = bias[n0], b1v = bias[n0 + 1];
            int r0 = bm + wm + mt * 16 + g;
            C[(size_t)r0 * N + n0]           = acc[mt][nt][0] + b0v;
            C[(size_t)r0 * N + n0 + 1]       = acc[mt][nt][1] + b1v;
            C[(size_t)(r0 + 8) * N + n0]     = acc[mt][nt][2] + b0v;
            C[(size_t)(r0 + 8) * N + n0 + 1] = acc[mt][nt][3] + b1v;
        }
    }
}

// ---------------------------------------------------------------------------
// Scores: attn[b,h,t,s] = (Q.K)/8 + mask, kpm==0 -> -inf
// Block 128(t) x 128(s), 8 warps (2x4), single-shot K=64, one sync.
// Dynamic smem: Q [128][68] + K [128][68] fp32 = 69632 B.
// ---------------------------------------------------------------------------
__global__ __launch_bounds__(256, 2) void score_tc(
    const float* __restrict__ Q, const float* __restrict__ Kp,
    const float* __restrict__ attn_mask, const int* __restrict__ kpm,
    float* __restrict__ attn)
{
    extern __shared__ float dsm[];
    float* Qs = dsm;              // [128][68]
    float* Ks = dsm + 128 * 68;   // [128][68]  (n-major: [s][d])
    const uint32_t qbase = (uint32_t)__cvta_generic_to_shared(Qs);
    const uint32_t kbase = (uint32_t)__cvta_generic_to_shared(Ks);

    const int tid = threadIdx.x;
    const int wid = tid >> 5, lane = tid & 31;
    const int g = lane >> 2, tg = lane & 3;
    const int bh = blockIdx.z;
    const int b = bh >> 3, h = bh & 7;
    const int t0 = blockIdx.y * 128, s0 = blockIdx.x * 128;
    const int wm = (wid >> 2) * 64, wn = (wid & 3) * 32;

    // Load Q and K tiles (each 128 rows x 256B)
    #pragma unroll
    for (int i = tid; i < 128 * 16; i += 256) {
        int r = i >> 4, seg = i & 15;
        cp_async16(qbase + (r * 68 + seg * 4) * 4,
                   Q + (size_t)(b * T_ + t0 + r) * DQ_ + h * HD_ + seg * 4);
        cp_async16(kbase + (r * 68 + seg * 4) * 4,
                   Kp + (size_t)(b * S_ + s0 + r) * DQ_ + h * HD_ + seg * 4);
    }
    cp_commit();
    cp_wait0();
    __syncthreads();

    float acc[4][4][4];
    #pragma unroll
    for (int mt = 0; mt < 4; mt++)
        #pragma unroll
        for (int nt = 0; nt < 4; nt++)
            #pragma unroll
            for (int r = 0; r < 4; r++) acc[mt][nt][r] = 0.f;

    #pragma unroll
    for (int ks = 0; ks < 8; ks++) {
        const int kk = ks * 8;
        uint32_t a[4][4], bf[4][2];
        #pragma unroll
        for (int mt = 0; mt < 4; mt++) {
            int mr = wm + mt * 16;
            a[mt][0] = ldtf(Qs + (mr + g) * 68 + kk + tg);
            a[mt][1] = ldtf(Qs + (mr + g + 8) * 68 + kk + tg);
            a[mt][2] = ldtf(Qs + (mr + g) * 68 + kk + tg + 4);
            a[mt][3] = ldtf(Qs + (mr + g + 8) * 68 + kk + tg + 4);
        }
        #pragma unroll
        for (int nt = 0; nt < 4; nt++) {
            int nc = wn + nt * 8 + g;
            bf[nt][0] = ldtf(Ks + nc * 68 + kk + tg);
            bf[nt][1] = ldtf(Ks + nc * 68 + kk + tg + 4);
        }
        #pragma unroll
        for (int mt = 0; mt < 4; mt++)
            #pragma unroll
            for (int nt = 0; nt < 4; nt++)
                mma_tf32(acc[mt][nt], a[mt][0], a[mt][1], a[mt][2], a[mt][3],
                         bf[nt][0], bf[nt][1]);
    }

    // Epilogue: scale + mask + kpm
    #pragma unroll
    for (int mt = 0; mt < 4; mt++) {
        #pragma unroll
        for (int nt = 0; nt < 4; nt++) {
            int s = s0 + wn + nt * 8 + tg * 2;
            int kp0 = kpm[b * S_ + s], kp1 = kpm[b * S_ + s + 1];
            int t = t0 + wm + mt * 16 + g;
            #pragma unroll
            for (int half = 0; half < 2; half++) {
                int tr = t + half * 8;
                float v0 = acc[mt][nt][half * 2]     * 0.125f + attn_mask[(size_t)tr * S_ + s];
                float v1 = acc[mt][nt][half * 2 + 1] * 0.125f + attn_mask[(size_t)tr * S_ + s + 1];
                if (kp0 == 0) v0 = -INFINITY;
                if (kp1 == 0) v1 = -INFINITY;
                attn[((size_t)bh * T_ + tr) * S_ + s]     = v0;
                attn[((size_t)bh * T_ + tr) * S_ + s + 1] = v1;
            }
        }
    }
}

// ---------------------------------------------------------------------------
// In-place row softmax over S=2048.
// ---------------------------------------------------------------------------
__global__ __launch_bounds__(256) void softmax_kernel(float* __restrict__ attn)
{
    size_t row = blockIdx.x;
    float* p = attn + row * (size_t)S_;
    int tid = threadIdx.x;

    float v[8];
    #pragma unroll
    for (int i = 0; i < 8; i++) v[i] = p[tid + 256 * i];

    float m = v[0];
    #pragma unroll
    for (int i = 1; i < 8; i++) m = fmaxf(m, v[i]);
    #pragma unroll
    for (int o = 16; o > 0; o >>= 1) m = fmaxf(m, __shfl_xor_sync(0xffffffffu, m, o));

    __shared__ float red[8];
    if ((tid & 31) == 0) red[tid >> 5] = m;
    __syncthreads();
    if (tid < 32) {
        float x = (tid < 8) ? red[tid] : -INFINITY;
        #pragma unroll
        for (int o = 4; o > 0; o >>= 1) x = fmaxf(x, __shfl_xor_sync(0xffffffffu, x, o));
        if (tid == 0) red[0] = x;
    }
    __syncthreads();
    m = red[0];
    __syncthreads();

    float s = 0.f;
    #pragma unroll
    for (int i = 0; i < 8; i++) { v[i] = __expf(v[i] - m); s += v[i]; }
    #pragma unroll
    for (int o = 16; o > 0; o >>= 1) s += __shfl_xor_sync(0xffffffffu, s, o);
    if ((tid & 31) == 0) red[tid >> 5] = s;
    __syncthreads();
    if (tid < 32) {
        float x = (tid < 8) ? red[tid] : 0.f;
        #pragma unroll
        for (int o = 4; o > 0; o >>= 1) x += __shfl_xor_sync(0xffffffffu, x, o);
        if (tid == 0) red[0] = x;
    }
    __syncthreads();
    float inv = 1.0f / red[0];

    #pragma unroll
    for (int i = 0; i < 8; i++) p[tid + 256 * i] = v[i] * inv;
}

// ---------------------------------------------------------------------------
// ctx[b,t,h,:] = attn[b,h,t,:] @ V[b,:,h,:]
// Block 128(t) x 64(d), 4 warps (2x2), BK=32 over S, cp.async double-buffered.
// ---------------------------------------------------------------------------
__global__ __launch_bounds__(128, 4) void av_tc(
    const float* __restrict__ attn, const float* __restrict__ Vp,
    float* __restrict__ ctx)
{
    extern __shared__ float dsm[];
    float* As = dsm;                    // [2][128][36]
    float* Bs = dsm + 2 * 128 * 36;     // [2][32][68]
    const uint32_t abase = (uint32_t)__cvta_generic_to_shared(As);
    const uint32_t bbase = (uint32_t)__cvta_generic_to_shared(Bs);

    const int tid = threadIdx.x;
    const int wid = tid >> 5, lane = tid & 31;
    const int g = lane >> 2, tg = lane & 3;
    const int bh = blockIdx.y;
    const int b = bh >> 3, h = bh & 7;
    const int t0 = blockIdx.x * 128;
    const int wm = (wid >> 1) * 64, wn = (wid & 1) * 32;

    const float* arow = attn + ((size_t)bh * T_ + t0) * S_;

    float acc[4][4][4];
    #pragma unroll
    for (int mt = 0; mt < 4; mt++)
        #pragma unroll
        for (int nt = 0; nt < 4; nt++)
            #pragma unroll
            for (int r = 0; r < 4; r++) acc[mt][nt][r] = 0.f;

    auto load_stage = [&](int buf, int k0) {
        uint32_t ab = abase + (uint32_t)buf * 128 * 36 * 4;
        #pragma unroll
        for (int i = tid; i < 128 * 8; i += 128) {
            int r = i >> 3, seg = i & 7;
            cp_async16(ab + (r * 36 + seg * 4) * 4,
                       arow + (size_t)r * S_ + k0 + seg * 4);
        }
        uint32_t bb = bbase + (uint32_t)buf * 32 * 68 * 4;
        #pragma unroll
        for (int i = tid; i < 32 * 16; i += 128) {
            int r = i >> 4, seg = i & 15;
            cp_async16(bb + (r * 68 + seg * 4) * 4,
                       Vp + (size_t)(b * S_ + k0 + r) * DQ_ + h * HD_ + seg * 4);
        }
        cp_commit();
    };

    load_stage(0, 0);
    int buf = 0;
    for (int k0 = 0; k0 < S_; k0 += 32, buf ^= 1) {
        cp_wait0();
        __syncthreads();
        if (k0 + 32 < S_) load_stage(buf ^ 1, k0 + 32);

        const float* Ab = As + buf * 128 * 36;
        const float* Bb = Bs + buf * 32 * 68;
        #pragma unroll
        for (int ks = 0; ks < 4; ks++) {
            const int kk = ks * 8;
            uint32_t a[4][4], bf[4][2];
            #pragma unroll
            for (int mt = 0; mt < 4; mt++) {
                int mr = wm + mt * 16;
                a[mt][0] = ldtf(Ab + (mr + g) * 36 + kk + tg);
                a[mt][1] = ldtf(Ab + (mr + g + 8) * 36 + kk + tg);
                a[mt][2] = ldtf(Ab + (mr + g) * 36 + kk + tg + 4);
                a[mt][3] = ldtf(Ab + (mr + g + 8) * 36 + kk + tg + 4);
            }
            #pragma unroll
            for (int nt = 0; nt < 4; nt++) {
                int nc = wn + nt * 8 + g;
                bf[nt][0] = ldtf(Bb + (kk + tg) * 68 + nc);
                bf[nt][1] = ldtf(Bb + (kk + tg + 4) * 68 + nc);
            }
            #pragma unroll
            for (int mt = 0; mt < 4; mt++)
                #pragma unroll
                for (int nt = 0; nt < 4; nt++)
                    mma_tf32(acc[mt][nt], a[mt][0], a[mt][1], a[mt][2], a[mt][3],
                             bf[nt][0], bf[nt][1]);
        }
    }

    #pragma unroll
    for (int mt = 0; mt < 4; mt++) {
        #pragma unroll
        for (int nt = 0; nt < 4; nt++) {
            int d0 = wn + nt * 8 + tg * 2;
            int t = t0 + wm + mt * 16 + g;
            ctx[(size_t)(b * T_ + t) * DQ_ + h * HD_ + d0]         = acc[mt][nt][0];
            ctx[(size_t)(b * T_ + t) * DQ_ + h * HD_ + d0 + 1]     = acc[mt][nt][1];
            ctx[(size_t)(b * T_ + t + 8) * DQ_ + h * HD_ + d0]     = acc[mt][nt][2];
            ctx[(size_t)(b * T_ + t + 8) * DQ_ + h * HD_ + d0 + 1] = acc[mt][nt][3];
        }
    }
}

// ---------------------------------------------------------------------------
// Launch
// ---------------------------------------------------------------------------
extern "C" void kernel_launch(void* const* d_in, const int* in_sizes, int n_in,
                              void* d_out, int out_size)
{
    const float* query     = (const float*)d_in[0];
    const float* key       = (const float*)d_in[1];
    const float* value     = (const float*)d_in[2];
    const int*   kpm       = (const int*)  d_in[3];
    const float* attn_mask = (const float*)d_in[4];
    const float* Wq = (const float*)d_in[5];
    const float* bq = (const float*)d_in[6];
    const float* Wk = (const float*)d_in[7];
    const float* bk = (const float*)d_in[8];
    const float* Wv = (const float*)d_in[9];
    const float* bv = (const float*)d_in[10];
    const float* Wo = (const float*)d_in[11];
    const float* bo = (const float*)d_in[12];

    float* out  = (float*)d_out;                        // [B,T,DQ]
    float* attn = out + (size_t)B_ * T_ * DQ_;          // [B,H,T,S]

    float *Qp, *Kp, *Vp, *Cp;
    cudaGetSymbolAddress((void**)&Qp, g_Q);
    cudaGetSymbolAddress((void**)&Kp, g_K);
    cudaGetSymbolAddress((void**)&Vp, g_V);
    cudaGetSymbolAddress((void**)&Cp, g_ctx);

    const int GEMM_SMEM  = (2 * 128 * 36 + 2 * 32 * 68) * 4;   // 54272
    const int SCORE_SMEM = (2 * 128 * 68) * 4;                  // 69632

    static int attr_done = 0;
    if (!attr_done) {
        cudaFuncSetAttribute(gemm_bias_tc, cudaFuncAttributeMaxDynamicSharedMemorySize, GEMM_SMEM);
        cudaFuncSetAttribute(score_tc,     cudaFuncAttributeMaxDynamicSharedMemorySize, SCORE_SMEM);
        cudaFuncSetAttribute(av_tc,        cudaFuncAttributeMaxDynamicSharedMemorySize, GEMM_SMEM);
        attr_done = 1;
    }

    const int M = B_ * T_;   // 8192

    // Projections (tf32 tensor cores, cp.async pipelined)
    gemm_bias_tc<<<dim3(DQ_ / 64, M / 128), 128, GEMM_SMEM>>>(query, Wq, bq, Qp, M, DQ_, DQ_);
    gemm_bias_tc<<<dim3(DQ_ / 64, M / 128), 128, GEMM_SMEM>>>(key,   Wk, bk, Kp, M, DQ_, DKV_);
    gemm_bias_tc<<<dim3(DQ_ / 64, M / 128), 128, GEMM_SMEM>>>(value, Wv, bv, Vp, M, DQ_, DKV_);

    // Scores + mask -> attn region of d_out
    score_tc<<<dim3(S_ / 128, T_ / 128, B_ * H_), 256, SCORE_SMEM>>>(Qp, Kp, attn_mask, kpm, attn);

    // Row softmax in place
    softmax_kernel<<<B_ * H_ * T_, 256>>>(attn);

    // attn @ V -> ctx
    av_tc<<<dim3(T_ / 128, B_ * H_), 128, GEMM_SMEM>>>(attn, Vp, Cp);

    // Output projection
    gemm_bias_tc<<<dim3(DQ_ / 64, M / 128), 128, GEMM_SMEM>>>(Cp, Wo, bo, out, M, DQ_, DQ_);
}